// round 14
// baseline (speedup 1.0000x reference)
#include <cuda_runtime.h>
#include <cstdint>

#define BATCH 4
#define NPTS  8192
#define NSETS 8                    // index = batch*2 + side (side 0 = a, 1 = b)
#define NPT_ALL 65536
#define G  32
#define G3 32768
#define CSROW (G3 + 4)             // padded row: keeps rows 16B-aligned
#define NBLK  256
#define NTHR  256
#define NWARP_ALL (NBLK * NTHR / 32)   // 2048

// ---- persistent state ----
__device__ unsigned int g_bmin[3] = {0xFFFFFFFFu, 0xFFFFFFFFu, 0xFFFFFFFFu};
__device__ unsigned int g_bmax[3] = {0u, 0u, 0u};
__device__ int    g_hist[NSETS][G3];
__device__ int    g_cellStart[NSETS][CSROW];   // [G3] = sentinel
__device__ int    g_writePtr[NSETS][G3];
__device__ int    g_tileSum[NSETS][32];
__device__ int    g_cellOf[NPT_ALL];
__device__ float4 g_sorted[NPT_ALL];
__device__ float  g_accArr[64];

// grid-barrier state: two-level counters + monotonic epoch (never reset)
__device__ int g_grpCnt[8][16];
__device__ int g_rootCnt[8];
__device__ volatile unsigned g_epoch;

__device__ __forceinline__ unsigned enc(float f) {
    unsigned u = __float_as_uint(f);
    return (u & 0x80000000u) ? ~u : (u | 0x80000000u);
}
__device__ __forceinline__ float dec(unsigned u) {
    return __uint_as_float((u & 0x80000000u) ? (u & 0x7FFFFFFFu) : ~u);
}
__device__ __forceinline__ int cclamp(int v) { return min(max(v, 0), G - 1); }

// two-level epoch barrier: 16 groups x 16 CTAs; one slot per use
__device__ __forceinline__ void grid_bar(int slot, unsigned target) {
    __syncthreads();
    if (threadIdx.x == 0) {
        __threadfence();
        int grp = blockIdx.x & 15;
        if (atomicAdd(&g_grpCnt[slot][grp], 1) == 15) {
            g_grpCnt[slot][grp] = 0;
            if (atomicAdd(&g_rootCnt[slot], 1) == 15) {
                g_rootCnt[slot] = 0;
                __threadfence();
                g_epoch = target;            // single writer at this point
            }
        }
        while ((int)(g_epoch - target) < 0) __nanosleep(64);
        __threadfence();
    }
    __syncthreads();
}

__global__ __launch_bounds__(NTHR, 2)
void chamfer_persist(const float* __restrict__ a, const float* __restrict__ b,
                     float* __restrict__ out) {
    __shared__ unsigned s_e0;
    __shared__ unsigned smin[3], smax[3];
    __shared__ int s_misc[64];

    const int tid  = threadIdx.x;
    const int gtid = blockIdx.x * NTHR + tid;     // 0..65535
    const int lane = tid & 31;

    if (tid == 0) s_e0 = g_epoch;
    if (tid < 3) { smin[tid] = 0xFFFFFFFFu; smax[tid] = 0u; }
    __syncthreads();
    const unsigned e0 = s_e0;

    // ================= P0: zero scratch + bbox =================
    ((int4*)g_hist)[gtid] = make_int4(0, 0, 0, 0);   // 65536 int4 = whole hist
    if (gtid < 64) g_accArr[gtid] = 0.0f;
    if (gtid < NSETS) g_cellStart[gtid][G3] = NPTS;  // sentinel

    {   // bbox: 196608 floats, 3 per thread; axis rotates since 65536 % 3 == 1
        const int total = BATCH * NPTS * 3;
        unsigned lmin[3] = {0xFFFFFFFFu, 0xFFFFFFFFu, 0xFFFFFFFFu};
        unsigned lmax[3] = {0u, 0u, 0u};
        for (int j = gtid; j < 2 * total; j += NBLK * NTHR) {
            float v = (j < total) ? a[j] : b[j - total];
            int axis = j % 3;
            unsigned e = enc(v);
            lmin[axis] = min(lmin[axis], e);
            lmax[axis] = max(lmax[axis], e);
        }
        #pragma unroll
        for (int ax = 0; ax < 3; ax++) {
            atomicMin(&smin[ax], lmin[ax]);
            atomicMax(&smax[ax], lmax[ax]);
        }
        __syncthreads();
        // NOTE: g_bmin/g_bmax are NOT reset: inputs are constant across
        // replays, so atomicMin/Max reconverges to identical values.
        if (tid < 3) {
            atomicMin(&g_bmin[tid], smin[tid]);
            atomicMax(&g_bmax[tid], smax[tid]);
        }
    }

    grid_bar(0, e0 + 1);

    // grid params (uniform across threads)
    const float lox = dec(g_bmin[0]), loy = dec(g_bmin[1]), loz = dec(g_bmin[2]);
    float ext = fmaxf(dec(g_bmax[0]) - lox,
                fmaxf(dec(g_bmax[1]) - loy, dec(g_bmax[2]) - loz)) * (1.0f + 1e-5f);
    const float h = ext / (float)G;
    const float inv_h = (float)G / ext;

    // ================= P1: histogram (1 point per thread) =================
    {
        int bs = gtid >> 13, i = gtid & (NPTS - 1);
        const float* base = (bs & 1) ? b : a;
        const float* p = base + ((size_t)((bs >> 1) * NPTS + i)) * 3;
        int cx = cclamp((int)((p[0] - lox) * inv_h));
        int cy = cclamp((int)((p[1] - loy) * inv_h));
        int cz = cclamp((int)((p[2] - loz) * inv_h));
        int cell = (cz * G + cy) * G + cx;
        g_cellOf[gtid] = cell;
        atomicAdd(&g_hist[bs][cell], 1);
    }

    grid_bar(1, e0 + 2);

    // ================= P2: per-tile scan (1 tile per CTA, 256 tiles) =========
    const int set  = blockIdx.x >> 5;
    const int tile = blockIdx.x & 31;
    {
        int warp = tid >> 5;
        int cell = tile * 1024 + tid * 4;
        int4 c = *(const int4*)&g_hist[set][cell];
        int s4 = c.x + c.y + c.z + c.w;
        int v = s4;
        #pragma unroll
        for (int off = 1; off < 32; off <<= 1) {
            int u = __shfl_up_sync(0xFFFFFFFFu, v, off);
            if (lane >= off) v += u;
        }
        if (lane == 31) s_misc[warp] = v;
        __syncthreads();
        if (tid == 0) {
            int run = 0;
            #pragma unroll
            for (int w2 = 0; w2 < 8; w2++) { int x = s_misc[w2]; s_misc[w2] = run; run += x; }
        }
        __syncthreads();
        int excl = v - s4 + s_misc[warp];
        int4 pfx;
        pfx.x = excl; pfx.y = pfx.x + c.x; pfx.z = pfx.y + c.y; pfx.w = pfx.z + c.z;
        *(int4*)&g_cellStart[set][cell] = pfx;
        if (tid == 255) g_tileSum[set][tile] = excl + s4;
        __syncthreads();
    }

    grid_bar(2, e0 + 3);

    // ================= P3: apply tile offsets, fill write ptrs ==============
    {
        if (tid < 32) {               // warp 0: exclusive prefix of 32 tile sums
            int v = g_tileSum[set][tid];
            int incl = v;
            #pragma unroll
            for (int off = 1; off < 32; off <<= 1) {
                int u = __shfl_up_sync(0xFFFFFFFFu, incl, off);
                if (tid >= off) incl += u;
            }
            s_misc[tid] = incl - v;
        }
        __syncthreads();
        int off = s_misc[tile];
        int cell = tile * 1024 + tid * 4;
        int4 p = *(const int4*)&g_cellStart[set][cell];
        p.x += off; p.y += off; p.z += off; p.w += off;
        *(int4*)&g_cellStart[set][cell] = p;
        *(int4*)&g_writePtr[set][cell]  = p;
        __syncthreads();
    }

    grid_bar(3, e0 + 4);

    // ================= P4: scatter (1 point per thread) =====================
    {
        int bs = gtid >> 13, i = gtid & (NPTS - 1);
        const float* base = (bs & 1) ? b : a;
        const float* p = base + ((size_t)((bs >> 1) * NPTS + i)) * 3;
        float x = p[0], y = p[1], z = p[2];
        int cell = g_cellOf[gtid];
        int pos = atomicAdd(&g_writePtr[bs][cell], 1);
        g_sorted[(bs << 13) + pos] = make_float4(x, y, z, 0.0f);
    }

    grid_bar(4, e0 + 5);

    // ================= P5: query — 2 queries per warp (half-warps) ==========
    {
        const int w    = gtid >> 5;         // global warp id, 0..2047
        const int qsel = lane >> 4;         // 0 or 1: which query of the pair
        const int hl   = lane & 15;         // lane within half-warp
        const float h99 = h * 0.9999f;
        float acc = 0.0f;

        for (int k = 0; k < 16; k++) {
            int qid = ((k * NWARP_ALL + w) << 1) | qsel;
            int bs = qid >> 13;
            const float4* refp = g_sorted + ((bs ^ 1) << 13);
            const int*    cs   = g_cellStart[bs ^ 1];
            float4 q = g_sorted[qid];
            int qx = cclamp((int)((q.x - lox) * inv_h));
            int qy = cclamp((int)((q.y - loy) * inv_h));
            int qz = cclamp((int)((q.z - loz) * inv_h));

            float best = 3.4e38f;

            // radius-1 box: 27 cells over 16 lanes of this half
            for (int c = hl; c < 27; c += 16) {
                int dz = c / 9, rem = c - dz * 9;
                int dy = rem / 3, dx = rem - dy * 3;
                int cz = qz + dz - 1, cy = qy + dy - 1, cx = qx + dx - 1;
                if (((unsigned)cz < G) & ((unsigned)cy < G) & ((unsigned)cx < G)) {
                    int bidx = (cz * G + cy) * G + cx;
                    int s = cs[bidx], e = cs[bidx + 1];
                    for (int j = s; j < e; j++) {
                        float4 r = refp[j];
                        float dxf = q.x - r.x, dyf = q.y - r.y, dzf = q.z - r.z;
                        float d = dxf * dxf;
                        d = fmaf(dyf, dyf, d);
                        d = fmaf(dzf, dzf, d);
                        best = fminf(best, d);
                    }
                }
            }
            // half-warp min (offsets < 16 stay within the half)
            #pragma unroll
            for (int off = 8; off > 0; off >>= 1)
                best = fminf(best, __shfl_xor_sync(0xFFFFFFFFu, best, off));

            // rare: full-box rescans; after box radius m, unscanned >= m*h away
            for (int m = 2; m <= G; m++) {
                float bnd = (float)(m - 1) * h99;
                bool act = best > bnd * bnd;
                if (!__any_sync(0xFFFFFFFFu, act)) break;
                float pb = best;
                if (act) {
                    int W = 2 * m + 1;
                    int xlo = max(qx - m, 0), xhi = min(qx + m, G - 1);
                    for (int r = hl; r < W * W; r += 16) {
                        int rz = r / W, ry = r - rz * W;
                        int cz = qz - m + rz, cy = qy - m + ry;
                        if (((unsigned)cz < G) & ((unsigned)cy < G)) {
                            int rb = (cz * G + cy) * G;
                            int s = cs[rb + xlo], e = cs[rb + xhi + 1];
                            for (int j = s; j < e; j++) {
                                float4 rp = refp[j];
                                float dxf = q.x - rp.x, dyf = q.y - rp.y, dzf = q.z - rp.z;
                                float d = dxf * dxf;
                                d = fmaf(dyf, dyf, d);
                                d = fmaf(dzf, dzf, d);
                                pb = fminf(pb, d);
                            }
                        }
                    }
                }
                #pragma unroll
                for (int off = 8; off > 0; off >>= 1)
                    pb = fminf(pb, __shfl_xor_sync(0xFFFFFFFFu, pb, off));
                best = pb;
            }
            if (hl == 0) acc += best;       // lanes 0 and 16 hold the 2 results
        }

        // warp sum (only lanes 0,16 carry nonzero) then one atomic per warp
        #pragma unroll
        for (int off = 16; off > 0; off >>= 1)
            acc += __shfl_xor_sync(0xFFFFFFFFu, acc, off);
        if (lane == 0) atomicAdd(&g_accArr[w & 63], acc);
    }

    grid_bar(5, e0 + 6);

    // ================= P6: final reduce (CTA 0) =============================
    if (blockIdx.x == 0) {
        __shared__ float red[64];
        if (tid < 64) red[tid] = g_accArr[tid];
        __syncthreads();
        #pragma unroll
        for (int s = 32; s > 0; s >>= 1) {
            if (tid < s) red[tid] += red[tid + s];
            __syncthreads();
        }
        if (tid == 0) out[0] = red[0] * (1.0f / (float)(BATCH * NPTS));
    }
}

extern "C" void kernel_launch(void* const* d_in, const int* in_sizes, int n_in,
                              void* d_out, int out_size) {
    const float* a = (const float*)d_in[0];
    const float* b = (const float*)d_in[1];
    chamfer_persist<<<NBLK, NTHR>>>(a, b, (float*)d_out);
}

// round 17
// speedup vs baseline: 1.7902x; 1.7902x over previous
#include <cuda_runtime.h>
#include <cstdint>

#define BATCH 4
#define NPTS  8192
#define NSETS 8                    // index = batch*2 + side (side 0 = a, 1 = b)
#define NPT_ALL 65536
#define G  32
#define G3 32768
#define NTILES 32                  // G3 / 1024 scan tiles per set
#define CSROW (G3 + 4)             // padded row: keeps every row 16B-aligned

// ---- static scratch (re-initialized every launch sequence) ----
__device__ unsigned int g_bmin[3], g_bmax[3];
__device__ int    g_hist[NSETS][G3];
__device__ int    g_cellStart[NSETS][CSROW];   // [G3] = sentinel (NPTS)
__device__ int    g_writePtr[NSETS][G3];
__device__ int    g_tileSum[NSETS][NTILES];
__device__ int    g_cellOf[NPT_ALL];           // cached cell index per point
__device__ float4 g_sorted[NPT_ALL];           // cell-sorted points
__device__ float  g_accArr[64];

// order-preserving float<->uint encoding for atomic min/max
__device__ __forceinline__ unsigned int enc(float f) {
    unsigned int u = __float_as_uint(f);
    return (u & 0x80000000u) ? ~u : (u | 0x80000000u);
}
__device__ __forceinline__ float dec(unsigned int u) {
    return __uint_as_float((u & 0x80000000u) ? (u & 0x7FFFFFFFu) : ~u);
}

struct GridP { float lox, loy, loz, inv_h, h; };
__device__ __forceinline__ GridP grid_params() {
    GridP g;
    g.lox = dec(g_bmin[0]); g.loy = dec(g_bmin[1]); g.loz = dec(g_bmin[2]);
    float ex = dec(g_bmax[0]) - g.lox;
    float ey = dec(g_bmax[1]) - g.loy;
    float ez = dec(g_bmax[2]) - g.loz;
    float e = fmaxf(ex, fmaxf(ey, ez)) * (1.0f + 1e-5f);
    g.h = e / (float)G;
    g.inv_h = (float)G / e;
    return g;
}
__device__ __forceinline__ int cclamp(int v) { return min(max(v, 0), G - 1); }

__device__ __forceinline__ int cell_of(GridP g, float x, float y, float z) {
    int cx = cclamp((int)((x - g.lox) * g.inv_h));
    int cy = cclamp((int)((y - g.loy) * g.inv_h));
    int cz = cclamp((int)((z - g.loz) * g.inv_h));
    return (cz * G + cy) * G + cx;
}

// ---- k0: zero hist, sentinels, accumulators ----
__global__ void k0_init() {
    int i = blockIdx.x * blockDim.x + threadIdx.x;
    int stride = gridDim.x * blockDim.x;
    int4 z4 = make_int4(0, 0, 0, 0);
    for (int j = i; j < NSETS * G3 / 4; j += stride) ((int4*)g_hist)[j] = z4;
    if (i < 3)  { g_bmin[i] = 0xFFFFFFFFu; g_bmax[i] = 0u; }
    if (i < 64) g_accArr[i] = 0.0f;
    if (i < NSETS) g_cellStart[i][G3] = NPTS;   // sentinel
}

// ---- k1: bbox, 4 points per thread via coalesced float4 loads ----
__global__ __launch_bounds__(256)
void k1_bbox(const float* __restrict__ a, const float* __restrict__ b) {
    __shared__ unsigned int smin[3], smax[3];
    if (threadIdx.x < 3) { smin[threadIdx.x] = 0xFFFFFFFFu; smax[threadIdx.x] = 0u; }
    __syncthreads();

    int tid = blockIdx.x * blockDim.x + threadIdx.x;   // < 16384
    int bs = tid >> 11;                  // 2048 groups of 4 pts per set
    int j  = tid & 2047;
    const float* base = (bs & 1) ? b : a;
    const float4* src = (const float4*)(base + (size_t)(bs >> 1) * NPTS * 3) + j * 3;
    float4 v0 = src[0], v1 = src[1], v2 = src[2];

    // 4 points: (v0.x v0.y v0.z) (v0.w v1.x v1.y) (v1.z v1.w v2.x) (v2.y v2.z v2.w)
    unsigned xmn = min(min(enc(v0.x), enc(v0.w)), min(enc(v1.z), enc(v2.y)));
    unsigned xmx = max(max(enc(v0.x), enc(v0.w)), max(enc(v1.z), enc(v2.y)));
    unsigned ymn = min(min(enc(v0.y), enc(v1.x)), min(enc(v1.w), enc(v2.z)));
    unsigned ymx = max(max(enc(v0.y), enc(v1.x)), max(enc(v1.w), enc(v2.z)));
    unsigned zmn = min(min(enc(v0.z), enc(v1.y)), min(enc(v2.x), enc(v2.w)));
    unsigned zmx = max(max(enc(v0.z), enc(v1.y)), max(enc(v2.x), enc(v2.w)));

    atomicMin(&smin[0], xmn); atomicMax(&smax[0], xmx);
    atomicMin(&smin[1], ymn); atomicMax(&smax[1], ymx);
    atomicMin(&smin[2], zmn); atomicMax(&smax[2], zmx);
    __syncthreads();
    if (threadIdx.x < 3) {
        atomicMin(&g_bmin[threadIdx.x], smin[threadIdx.x]);
        atomicMax(&g_bmax[threadIdx.x], smax[threadIdx.x]);
    }
}

// ---- k2: histogram, 4 points per thread via coalesced float4 loads ----
__global__ __launch_bounds__(256)
void k2_hist(const float* __restrict__ a, const float* __restrict__ b) {
    int tid = blockIdx.x * blockDim.x + threadIdx.x;   // < 16384
    GridP g = grid_params();
    int bs = tid >> 11;
    int j  = tid & 2047;
    const float* base = (bs & 1) ? b : a;
    const float4* src = (const float4*)(base + (size_t)(bs >> 1) * NPTS * 3) + j * 3;
    float4 v0 = src[0], v1 = src[1], v2 = src[2];

    int c0 = cell_of(g, v0.x, v0.y, v0.z);
    int c1 = cell_of(g, v0.w, v1.x, v1.y);
    int c2 = cell_of(g, v1.z, v1.w, v2.x);
    int c3 = cell_of(g, v2.y, v2.z, v2.w);

    atomicAdd(&g_hist[bs][c0], 1);
    atomicAdd(&g_hist[bs][c1], 1);
    atomicAdd(&g_hist[bs][c2], 1);
    atomicAdd(&g_hist[bs][c3], 1);
    *(int4*)&g_cellOf[(bs << 13) + j * 4] = make_int4(c0, c1, c2, c3);
}

// ---- k3a: per-tile exclusive scan (coalesced, shfl-based) ----
__global__ __launch_bounds__(256)
void k3a_tilescan() {
    __shared__ int wsum[8];
    int set  = blockIdx.x >> 5;
    int tile = blockIdx.x & 31;
    int t = threadIdx.x, lane = t & 31, warp = t >> 5;
    int cell = tile * 1024 + t * 4;

    int4 c = *(const int4*)&g_hist[set][cell];
    int s4 = c.x + c.y + c.z + c.w;

    int v = s4;
    #pragma unroll
    for (int off = 1; off < 32; off <<= 1) {
        int u = __shfl_up_sync(0xFFFFFFFFu, v, off);
        if (lane >= off) v += u;
    }
    if (lane == 31) wsum[warp] = v;
    __syncthreads();
    if (t == 0) {
        int run = 0;
        #pragma unroll
        for (int w = 0; w < 8; w++) { int x = wsum[w]; wsum[w] = run; run += x; }
    }
    __syncthreads();

    int excl = v - s4 + wsum[warp];
    int4 p;
    p.x = excl; p.y = p.x + c.x; p.z = p.y + c.y; p.w = p.z + c.z;
    *(int4*)&g_cellStart[set][cell] = p;
    if (t == 255) g_tileSum[set][tile] = excl + s4;
}

// ---- k3b: scan tile sums in-CTA (R14 P3 pattern), apply, fill write ptrs ----
__global__ __launch_bounds__(256)
void k3b_finalize() {
    __shared__ int s_off[NTILES];
    int set  = blockIdx.x >> 5;
    int tile = blockIdx.x & 31;
    int t = threadIdx.x;

    if (t < 32) {                 // warp 0: exclusive prefix of the 32 tile sums
        int v = g_tileSum[set][t];
        int incl = v;
        #pragma unroll
        for (int off = 1; off < 32; off <<= 1) {
            int u = __shfl_up_sync(0xFFFFFFFFu, incl, off);
            if (t >= off) incl += u;
        }
        s_off[t] = incl - v;
    }
    __syncthreads();

    int off  = s_off[tile];
    int cell = tile * 1024 + t * 4;
    int4 p = *(const int4*)&g_cellStart[set][cell];
    p.x += off; p.y += off; p.z += off; p.w += off;
    *(int4*)&g_cellStart[set][cell] = p;
    *(int4*)&g_writePtr[set][cell]  = p;
}

// ---- k4: scatter, 4 points per thread (cells cached, coalesced loads) ----
__global__ __launch_bounds__(256)
void k4_scatter(const float* __restrict__ a, const float* __restrict__ b) {
    int tid = blockIdx.x * blockDim.x + threadIdx.x;   // < 16384
    int bs = tid >> 11;
    int j  = tid & 2047;
    const float* base = (bs & 1) ? b : a;
    const float4* src = (const float4*)(base + (size_t)(bs >> 1) * NPTS * 3) + j * 3;
    float4 v0 = src[0], v1 = src[1], v2 = src[2];
    int4 c = *(const int4*)&g_cellOf[(bs << 13) + j * 4];

    int p0 = atomicAdd(&g_writePtr[bs][c.x], 1);
    int p1 = atomicAdd(&g_writePtr[bs][c.y], 1);
    int p2 = atomicAdd(&g_writePtr[bs][c.z], 1);
    int p3 = atomicAdd(&g_writePtr[bs][c.w], 1);

    int sbase = bs << 13;
    g_sorted[sbase + p0] = make_float4(v0.x, v0.y, v0.z, 0.0f);
    g_sorted[sbase + p1] = make_float4(v0.w, v1.x, v1.y, 0.0f);
    g_sorted[sbase + p2] = make_float4(v1.z, v1.w, v2.x, 0.0f);
    g_sorted[sbase + p3] = make_float4(v2.y, v2.z, v2.w, 0.0f);
}

__device__ __forceinline__ float warp_min(float v) {
    #pragma unroll
    for (int off = 16; off > 0; off >>= 1)
        v = fminf(v, __shfl_xor_sync(0xFFFFFFFFu, v, off));
    return v;
}

// ---- k5: exact NN, warp per query, lane-parallel cell scanning ----
__global__ __launch_bounds__(128)
void k5_query() {
    __shared__ float ws[4];
    int gwid = (blockIdx.x * blockDim.x + threadIdx.x) >> 5;   // query id
    int lane = threadIdx.x & 31;
    GridP g = grid_params();

    int bs = gwid >> 13;
    int ref_bs = bs ^ 1;
    float4 q = g_sorted[gwid];
    int qx = cclamp((int)((q.x - g.lox) * g.inv_h));
    int qy = cclamp((int)((q.y - g.loy) * g.inv_h));
    int qz = cclamp((int)((q.z - g.loz) * g.inv_h));

    const float4* refp = g_sorted + (ref_bs << 13);
    const int*    cs   = g_cellStart[ref_bs];

    float best = 3.4e38f;

    // radius-1 box: one cell per lane (27 cells, one latency batch)
    if (lane < 27) {
        int dz = lane / 9, rem = lane - dz * 9;
        int dy = rem / 3,  dx = rem - dy * 3;
        int cz = qz + dz - 1, cy = qy + dy - 1, cx = qx + dx - 1;
        if (((unsigned)cz < G) & ((unsigned)cy < G) & ((unsigned)cx < G)) {
            int base = (cz * G + cy) * G + cx;
            int s = cs[base], e = cs[base + 1];
            for (int j = s; j < e; j++) {
                float4 r = refp[j];
                float dxf = q.x - r.x, dyf = q.y - r.y, dzf = q.z - r.z;
                float d = dxf * dxf;
                d = fmaf(dyf, dyf, d);
                d = fmaf(dzf, dzf, d);
                best = fminf(best, d);
            }
        }
    }
    best = warp_min(best);

    // rare: expand by full-box rescans, lane-per-row
    // After scanning box radius m, unscanned points are >= m*h away.
    float h99 = g.h * 0.9999f;
    for (int m = 2; m <= G; m++) {
        float bnd = (float)(m - 1) * h99;
        if (best <= bnd * bnd) break;
        float pb = best;
        int W = 2 * m + 1;
        int nrows = W * W;
        int xlo = max(qx - m, 0), xhi = min(qx + m, G - 1);
        for (int r = lane; r < nrows; r += 32) {
            int rz = r / W, ry = r - rz * W;
            int cz = qz - m + rz, cy = qy - m + ry;
            if (((unsigned)cz >= G) | ((unsigned)cy >= G)) continue;
            int rowbase = (cz * G + cy) * G;
            int s = cs[rowbase + xlo], e = cs[rowbase + xhi + 1];
            for (int j = s; j < e; j++) {
                float4 rp = refp[j];
                float dxf = q.x - rp.x, dyf = q.y - rp.y, dzf = q.z - rp.z;
                float d = dxf * dxf;
                d = fmaf(dyf, dyf, d);
                d = fmaf(dzf, dzf, d);
                pb = fminf(pb, d);
            }
        }
        best = warp_min(pb);
    }

    if (lane == 0) ws[threadIdx.x >> 5] = best;
    __syncthreads();
    if (threadIdx.x == 0) {
        float s = ws[0] + ws[1] + ws[2] + ws[3];
        atomicAdd(&g_accArr[blockIdx.x & 63], s);
    }
}

__global__ void k6_final(float* __restrict__ out) {
    __shared__ float red[64];
    red[threadIdx.x] = g_accArr[threadIdx.x];
    __syncthreads();
    #pragma unroll
    for (int s = 32; s > 0; s >>= 1) {
        if (threadIdx.x < s) red[threadIdx.x] += red[threadIdx.x + s];
        __syncthreads();
    }
    if (threadIdx.x == 0) out[0] = red[0] * (1.0f / (float)(BATCH * NPTS));
}

extern "C" void kernel_launch(void* const* d_in, const int* in_sizes, int n_in,
                              void* d_out, int out_size) {
    const float* a = (const float*)d_in[0];
    const float* b = (const float*)d_in[1];

    k0_init<<<64, 1024>>>();
    k1_bbox<<<NPT_ALL / 4 / 256, 256>>>(a, b);
    k2_hist<<<NPT_ALL / 4 / 256, 256>>>(a, b);
    k3a_tilescan<<<NSETS * NTILES, 256>>>();
    k3b_finalize<<<NSETS * NTILES, 256>>>();
    k4_scatter<<<NPT_ALL / 4 / 256, 256>>>(a, b);
    k5_query<<<NPT_ALL * 32 / 128, 128>>>();   // one warp per query
    k6_final<<<1, 64>>>((float*)d_out);
}